// round 2
// baseline (speedup 1.0000x reference)
#include <cuda_runtime.h>
#include <cuda_bf16.h>
#include <math.h>

// Problem constants
#define B_  32
#define N_  4096
#define C_  512
#define EPS_INV 10.0f          // 1/EPS_SINKHORN

#define CHUNKS 32              // chunks per batch
#define ROWS_PER_BLOCK (N_ / CHUNKS)   // 128
#define THREADS1 256           // 8 warps
#define NWARPS (THREADS1 / 32)

// Scratch (allocation-free rule: __device__ globals)
__device__ float g_vec[B_ * CHUNKS * C_];   // partial weighted sums: 2 MB
__device__ float g_E[B_ * CHUNKS];          // partial exp-sums

// ---------------------------------------------------------------------------
// Pass 1: stream visual_feats once. Per row: norm, cosine with prompt,
// w = exp(10*(s-1)) (shift m=0 valid since s<=1), accumulate w*vf and w.
// ---------------------------------------------------------------------------
__global__ __launch_bounds__(THREADS1)
void uot_pass1(const float* __restrict__ prompt,
               const float* __restrict__ vfeats)
{
    const int b     = blockIdx.x / CHUNKS;
    const int chunk = blockIdx.x % CHUNKS;
    const int tid   = threadIdx.x;
    const int wid   = tid >> 5;
    const int lane  = tid & 31;

    __shared__ float sp[C_];                 // raw prompt row
    __shared__ float sacc[NWARPS][C_];       // per-warp partial vector sums
    __shared__ float sEw[NWARPS];
    __shared__ float s_pinv;                 // 1/|p|

    // Load prompt row + compute its norm
    float ss = 0.f;
    #pragma unroll
    for (int i = tid; i < C_; i += THREADS1) {
        float v = prompt[b * C_ + i];
        sp[i] = v;
        ss += v * v;
    }
    #pragma unroll
    for (int o = 16; o; o >>= 1) ss += __shfl_xor_sync(0xffffffffu, ss, o);
    if (lane == 0) sEw[wid] = ss;            // reuse sEw as temp
    __syncthreads();
    if (tid == 0) {
        float t = 0.f;
        #pragma unroll
        for (int w = 0; w < NWARPS; w++) t += sEw[w];
        s_pinv = rsqrtf(fmaxf(t, 1e-24f));
    }
    __syncthreads();
    const float pinv = s_pinv;

    // Main streaming loop: each warp takes rows wid, wid+8, ... within chunk
    float acc[16];
    #pragma unroll
    for (int i = 0; i < 16; i++) acc[i] = 0.f;
    float Eacc = 0.f;

    const float4* pr4 = (const float4*)sp;
    const float* base = vfeats + ((size_t)b * N_ + (size_t)chunk * ROWS_PER_BLOCK) * C_;

    for (int r = wid; r < ROWS_PER_BLOCK; r += NWARPS) {
        const float4* row = (const float4*)(base + (size_t)r * C_);
        float4 v[4];
        float dpv = 0.f, dvv = 0.f;
        #pragma unroll
        for (int j = 0; j < 4; j++) {
            v[j] = row[j * 32 + lane];
            float4 p4 = pr4[j * 32 + lane];
            dpv += v[j].x * p4.x + v[j].y * p4.y + v[j].z * p4.z + v[j].w * p4.w;
            dvv += v[j].x * v[j].x + v[j].y * v[j].y + v[j].z * v[j].z + v[j].w * v[j].w;
        }
        #pragma unroll
        for (int o = 16; o; o >>= 1) {
            dpv += __shfl_xor_sync(0xffffffffu, dpv, o);
            dvv += __shfl_xor_sync(0xffffffffu, dvv, o);
        }
        float invn = rsqrtf(fmaxf(dvv, 1e-24f));
        float s    = dpv * invn * pinv;                 // cosine sim
        float e    = expf(EPS_INV * (s - 1.0f));        // shift m=0
        float w    = e * invn;                          // weight on RAW row
        Eacc += e;
        #pragma unroll
        for (int j = 0; j < 4; j++) {
            acc[j * 4 + 0] += w * v[j].x;
            acc[j * 4 + 1] += w * v[j].y;
            acc[j * 4 + 2] += w * v[j].z;
            acc[j * 4 + 3] += w * v[j].w;
        }
    }

    // Cross-warp combine in smem
    float4* sa4 = (float4*)sacc[wid];
    #pragma unroll
    for (int j = 0; j < 4; j++) {
        sa4[j * 32 + lane] = make_float4(acc[j*4+0], acc[j*4+1], acc[j*4+2], acc[j*4+3]);
    }
    __syncthreads();                   // also publishes prompt-norm temps done earlier
    if (lane == 0) sEw[wid] = Eacc;    // safe: all reads of old sEw done before sync
    __syncthreads();

    const int slot = b * CHUNKS + chunk;
    for (int c = tid; c < C_; c += THREADS1) {
        float s = 0.f;
        #pragma unroll
        for (int w = 0; w < NWARPS; w++) s += sacc[w][c];
        g_vec[slot * C_ + c] = s;
    }
    if (tid == 0) {
        float s = 0.f;
        #pragma unroll
        for (int w = 0; w < NWARPS; w++) s += sEw[w];
        g_E[slot] = s;
    }
}

// ---------------------------------------------------------------------------
// Pass 2: combine CHUNKS partials per batch, apply dustbin, write outputs.
// Output layout: [0 .. B*C) = obs_prompt, [B*C .. B*C+B) = total_mass.
// ---------------------------------------------------------------------------
__global__ __launch_bounds__(C_)
void uot_pass2(const float* __restrict__ dustbin_param,
               float* __restrict__ out)
{
    const int b   = blockIdx.x;
    const int tid = threadIdx.x;        // 512 threads, one per channel

    __shared__ float sE;
    if (tid < 32) {
        float e = g_E[b * CHUNKS + tid];   // CHUNKS == 32
        #pragma unroll
        for (int o = 16; o; o >>= 1) e += __shfl_xor_sync(0xffffffffu, e, o);
        if (tid == 0) sE = e;
    }
    __syncthreads();

    const float E    = sE;
    const float ebin = expf(-EPS_INV * dustbin_param[0]);
    const float S    = E + ebin;

    float num = 0.f;
    #pragma unroll
    for (int ch = 0; ch < CHUNKS; ch++)
        num += g_vec[(b * CHUNKS + ch) * C_ + tid];

    out[b * C_ + tid] = num / (E + 1e-6f * S);
    if (tid == 0) out[B_ * C_ + b] = E / S;
}

// ---------------------------------------------------------------------------
extern "C" void kernel_launch(void* const* d_in, const int* in_sizes, int n_in,
                              void* d_out, int out_size)
{
    const float* prompt  = (const float*)d_in[0];   // (32,1,512)
    const float* vfeats  = (const float*)d_in[1];   // (32,4096,512)
    // d_in[2] = dustbin_token : unused by the reference computation
    const float* dparam  = (const float*)d_in[3];   // (1,)
    float* out = (float*)d_out;

    uot_pass1<<<B_ * CHUNKS, THREADS1>>>(prompt, vfeats);
    uot_pass2<<<B_, C_>>>(dparam, out);
}